// round 6
// baseline (speedup 1.0000x reference)
#include <cuda_runtime.h>
#include <math.h>

#define N_NODES 25000
#define N_EDGES 400000
#define HID 64
#define HEADS 4
#define D1 (HID*HEADS)

typedef unsigned long long u64;

// ---------------- scratch (static device globals; no allocation) -------------
__device__ float g_h[N_NODES * HID];
__device__ float g_x[N_NODES * D1];
__device__ int   g_deg[N_NODES];
__device__ int   g_off[N_NODES + 1];
__device__ int   g_cur[N_NODES];
__device__ int   g_csr[N_EDGES];

// ---------------- helpers -----------------------------------------------------
__device__ __forceinline__ float ex2_approx(float x) {
    float r;
    asm("ex2.approx.ftz.f32 %0, %1;" : "=f"(r) : "f"(x));
    return r;
}
__device__ __forceinline__ u64 pk2(float lo, float hi) {
    u64 r; asm("mov.b64 %0, {%1, %2};" : "=l"(r) : "f"(lo), "f"(hi)); return r;
}
__device__ __forceinline__ void upk2(float& lo, float& hi, u64 v) {
    asm("mov.b64 {%0, %1}, %2;" : "=f"(lo), "=f"(hi) : "l"(v));
}
__device__ __forceinline__ u64 fma2(u64 a, u64 b, u64 c) {
    u64 r; asm("fma.rn.f32x2 %0, %1, %2, %3;" : "=l"(r) : "l"(a), "l"(b), "l"(c)); return r;
}
__device__ __forceinline__ u64 mul2(u64 a, u64 b) {
    u64 r; asm("mul.rn.f32x2 %0, %1, %2;" : "=l"(r) : "l"(a), "l"(b)); return r;
}
__device__ __forceinline__ u64 add2(u64 a, u64 b) {
    u64 r; asm("add.rn.f32x2 %0, %1, %2;" : "=l"(r) : "l"(a), "l"(b)); return r;
}

// ---------------- CSR build --------------------------------------------------
__global__ void k_count(const int* __restrict__ recv, int* __restrict__ deg, int E) {
    int i = blockIdx.x * blockDim.x + threadIdx.x;
    if (i < E) atomicAdd(&deg[recv[i]], 1);
}

__global__ __launch_bounds__(1024)
void k_scan(const int* __restrict__ deg, int* __restrict__ off,
            int* __restrict__ cur, int n) {
    __shared__ int wsum[32];
    __shared__ int carry_s;
    int t    = threadIdx.x;
    int lane = t & 31;
    int wid  = t >> 5;
    if (t == 0) { carry_s = 0; off[0] = 0; }
    __syncthreads();
    for (int base = 0; base < n; base += 1024) {
        int i = base + t;
        int v = (i < n) ? deg[i] : 0;
        int s = v;
#pragma unroll
        for (int o = 1; o < 32; o <<= 1) {
            int u = __shfl_up_sync(0xffffffffu, s, o);
            if (lane >= o) s += u;
        }
        if (lane == 31) wsum[wid] = s;
        __syncthreads();
        if (wid == 0) {
            int ws = wsum[lane];
#pragma unroll
            for (int o = 1; o < 32; o <<= 1) {
                int u = __shfl_up_sync(0xffffffffu, ws, o);
                if (lane >= o) ws += u;
            }
            wsum[lane] = ws;
        }
        __syncthreads();
        int prev  = (wid > 0) ? wsum[wid - 1] : 0;
        int carry = carry_s;
        int incl  = carry + prev + s;
        if (i < n) {
            off[i + 1] = incl;
            cur[i]     = incl - v;
        }
        __syncthreads();
        if (t == 1023) carry_s = incl;
        __syncthreads();
    }
}

__global__ void k_scatter(const int* __restrict__ recv, const int* __restrict__ send,
                          int* __restrict__ cur, int* __restrict__ csr,
                          int* __restrict__ deg, int E) {
    int i = blockIdx.x * blockDim.x + threadIdx.x;
    if (i < N_NODES) deg[i] = 0;
    if (i < E) {
        int r = recv[i];
        int p = atomicAdd(&cur[r], 1);
        csr[p] = send[i];
    }
}

// ---------------- GEMM v3: packed f32x2, 64x64 tile --------------------------
// 256 threads = 8 warps in 2(row-groups of 32) x 4(col-groups of 16).
// Thread: 4 rows (2 row-pair u64 accumulators) x 4 cols.
// A staged k-transposed (adjacent rows contiguous -> ulonglong2 LDS.128, no
// packing movs). B staged pre-duplicated as (b,b) u64 pairs (no dup movs).
// Inner loop per kk: 3x LDS.128 + 8x fma.rn.f32x2.
#define GKC 32
#define GAP 68   // padded A row (floats); 68*4=272 = 16B-aligned per kk ✓

__global__ __launch_bounds__(256, 4)
void k_gemm(const float* __restrict__ x, const float* __restrict__ Wq,
            const float* __restrict__ bq, float* __restrict__ h,
            int M, int K) {
    __shared__ float As[GKC * GAP];    // As[kk*GAP + m], m = local row
    __shared__ u64   Bs2[GKC * 64];    // Bs2[kk*64 + n] = (Wq[k][n], Wq[k][n])
    int t    = threadIdx.x;
    int lane = t & 31;
    int w    = t >> 5;
    int wr   = w & 1;                  // row-group (32 rows)
    int wc   = w >> 1;                 // col-group (16 cols)
    int r8   = lane & 7;               // 8 row positions
    int c4g  = lane >> 3;              // 4 col positions
    int rb   = wr * 32 + r8 * 4;       // local row base (4 rows)
    int cb   = wc * 16 + c4g * 4;      // local col base (4 cols)
    int m0   = blockIdx.x * 64;

    u64 acc[2][4];                     // [row-pair][col]
#pragma unroll
    for (int p = 0; p < 2; p++)
#pragma unroll
        for (int c = 0; c < 4; c++) acc[p][c] = 0ull;

    for (int k0 = 0; k0 < K; k0 += GKC) {
        // stage A: 64 rows x 32 k, transposed
#pragma unroll
        for (int i = 0; i < 2; i++) {
            int f  = t + i * 256;
            int r  = f >> 3;
            int c4 = (f & 7) * 4;
            int gr = m0 + r;
            float4 v = (gr < M) ? *(const float4*)&x[gr * K + k0 + c4]
                                : make_float4(0.f, 0.f, 0.f, 0.f);
            As[(c4 + 0) * GAP + r] = v.x;
            As[(c4 + 1) * GAP + r] = v.y;
            As[(c4 + 2) * GAP + r] = v.z;
            As[(c4 + 3) * GAP + r] = v.w;
        }
        // stage B duplicated
#pragma unroll
        for (int i = 0; i < 2; i++) {
            int f  = t + i * 256;
            int kk = f >> 4;
            int cc = (f & 15) * 4;
            float4 wv = *(const float4*)&Wq[(k0 + kk) * 64 + cc];
            Bs2[kk * 64 + cc + 0] = pk2(wv.x, wv.x);
            Bs2[kk * 64 + cc + 1] = pk2(wv.y, wv.y);
            Bs2[kk * 64 + cc + 2] = pk2(wv.z, wv.z);
            Bs2[kk * 64 + cc + 3] = pk2(wv.w, wv.w);
        }
        __syncthreads();
#pragma unroll
        for (int kk = 0; kk < GKC; kk++) {
            ulonglong2 a2  = *(const ulonglong2*)&As[kk * GAP + rb];      // rows rb..rb+3
            ulonglong2 b01 = *(const ulonglong2*)&Bs2[kk * 64 + cb];      // cols cb,cb+1
            ulonglong2 b23 = *(const ulonglong2*)&Bs2[kk * 64 + cb + 2];  // cols cb+2,cb+3
            acc[0][0] = fma2(a2.x, b01.x, acc[0][0]);
            acc[0][1] = fma2(a2.x, b01.y, acc[0][1]);
            acc[0][2] = fma2(a2.x, b23.x, acc[0][2]);
            acc[0][3] = fma2(a2.x, b23.y, acc[0][3]);
            acc[1][0] = fma2(a2.y, b01.x, acc[1][0]);
            acc[1][1] = fma2(a2.y, b01.y, acc[1][1]);
            acc[1][2] = fma2(a2.y, b23.x, acc[1][2]);
            acc[1][3] = fma2(a2.y, b23.y, acc[1][3]);
        }
        __syncthreads();
    }

    // epilogue: unpack row pairs, add bias, store 4 rows x 4 cols
    float4 bias = *(const float4*)&bq[cb];
#pragma unroll
    for (int p = 0; p < 2; p++) {
        float r0c0, r1c0, r0c1, r1c1, r0c2, r1c2, r0c3, r1c3;
        upk2(r0c0, r1c0, acc[p][0]);
        upk2(r0c1, r1c1, acc[p][1]);
        upk2(r0c2, r1c2, acc[p][2]);
        upk2(r0c3, r1c3, acc[p][3]);
        int gr0 = m0 + rb + 2 * p;
        if (gr0 < M) {
            float4 o = make_float4(r0c0 + bias.x, r0c1 + bias.y,
                                   r0c2 + bias.z, r0c3 + bias.w);
            *(float4*)&h[gr0 * HID + cb] = o;
        }
        if (gr0 + 1 < M) {
            float4 o = make_float4(r1c0 + bias.x, r1c1 + bias.y,
                                   r1c2 + bias.z, r1c3 + bias.w);
            *(float4*)&h[(gr0 + 1) * HID + cb] = o;
        }
    }
}

// ---------------- fused edge attention + aggregate (f32x2 packed) ------------
__global__ __launch_bounds__(256)
void k_edge(const float* __restrict__ h, const int* __restrict__ off,
            const int* __restrict__ csr, const float* __restrict__ Wl,
            const float* __restrict__ bl, float* __restrict__ out,
            int n, int last) {
    int w = (blockIdx.x * blockDim.x + threadIdx.x) >> 5;
    if (w >= n) return;
    int lane = threadIdx.x & 31;
    const u64* hv = (const u64*)h;

    float rvx, rvy;
    upk2(rvx, rvy, hv[w * 32 + lane]);

    const float L2E = 1.4426950408889634f;
    const u64 P02 = pk2(0.2f, 0.2f);
    u64 W0p[4], cp[4];
#pragma unroll
    for (int a = 0; a < 4; a++) {
        float w0 = Wl[a] * L2E;
        float w1 = Wl[4 + a];
        float b  = bl[a];
        W0p[a] = pk2(w0, w0);
        cp[a]  = pk2(fmaf(w1, rvx, b) * L2E, fmaf(w1, rvy, b) * L2E);
    }

    int beg = off[w], end = off[w + 1];
    bool has = end > beg;

    u64 den[4], num[4];
#pragma unroll
    for (int a = 0; a < 4; a++) { den[a] = pk2(0.f, 0.f); num[a] = pk2(0.f, 0.f); }

    int i = beg;
    for (; i + 2 <= end; i += 2) {
        int sa = __ldg(&csr[i]);
        int sb = __ldg(&csr[i + 1]);
        u64 pva = hv[sa * 32 + lane];
        u64 pvb = hv[sb * 32 + lane];
#pragma unroll
        for (int a = 0; a < 4; a++) {
            u64 z2 = fma2(W0p[a], pva, cp[a]);
            u64 zs = mul2(z2, P02);
            float zl, zh, sl, sh;
            upk2(zl, zh, z2); upk2(sl, sh, zs);
            float p0 = ex2_approx(fmaxf(zl, sl));
            float p1 = ex2_approx(fmaxf(zh, sh));
            u64 pp = pk2(p0, p1);
            den[a] = add2(den[a], pp);
            num[a] = fma2(pva, pp, num[a]);
        }
#pragma unroll
        for (int a = 0; a < 4; a++) {
            u64 z2 = fma2(W0p[a], pvb, cp[a]);
            u64 zs = mul2(z2, P02);
            float zl, zh, sl, sh;
            upk2(zl, zh, z2); upk2(sl, sh, zs);
            float p0 = ex2_approx(fmaxf(zl, sl));
            float p1 = ex2_approx(fmaxf(zh, sh));
            u64 pp = pk2(p0, p1);
            den[a] = add2(den[a], pp);
            num[a] = fma2(pvb, pp, num[a]);
        }
    }
    if (i < end) {
        int sa = __ldg(&csr[i]);
        u64 pva = hv[sa * 32 + lane];
#pragma unroll
        for (int a = 0; a < 4; a++) {
            u64 z2 = fma2(W0p[a], pva, cp[a]);
            u64 zs = mul2(z2, P02);
            float zl, zh, sl, sh;
            upk2(zl, zh, z2); upk2(sl, sh, zs);
            float p0 = ex2_approx(fmaxf(zl, sl));
            float p1 = ex2_approx(fmaxf(zh, sh));
            u64 pp = pk2(p0, p1);
            den[a] = add2(den[a], pp);
            num[a] = fma2(pva, pp, num[a]);
        }
    }

    if (last) {
        float acc0 = 0.f, acc1 = 0.f;
#pragma unroll
        for (int a = 0; a < 4; a++) {
            float n0, n1, d0, d1;
            upk2(n0, n1, num[a]); upk2(d0, d1, den[a]);
            acc0 += has ? __fdividef(n0, d0) : 0.f;
            acc1 += has ? __fdividef(n1, d1) : 0.f;
        }
        float v0 = 0.25f * acc0;
        float v1 = 0.25f * acc1;
        v0 = (v0 > 0.f) ? v0 : expm1f(v0);
        v1 = (v1 > 0.f) ? v1 : expm1f(v1);
        *(float2*)&out[w * HID + 2 * lane] = make_float2(v0, v1);
    } else {
        float o[8];
#pragma unroll
        for (int a = 0; a < 4; a++) {
            float n0, n1, d0, d1;
            upk2(n0, n1, num[a]); upk2(d0, d1, den[a]);
            float g0 = has ? __fdividef(n0, d0) : 0.f;
            float g1 = has ? __fdividef(n1, d1) : 0.f;
            o[a]     = (g0 > 0.f) ? g0 : expm1f(g0);
            o[4 + a] = (g1 > 0.f) ? g1 : expm1f(g1);
        }
        *(float4*)&out[w * D1 + 8 * lane]     = make_float4(o[0], o[1], o[2], o[3]);
        *(float4*)&out[w * D1 + 8 * lane + 4] = make_float4(o[4], o[5], o[6], o[7]);
    }
}

// ---------------- launch ------------------------------------------------------
extern "C" void kernel_launch(void* const* d_in, const int* in_sizes, int n_in,
                              void* d_out, int out_size) {
    const float* nodes = (const float*)d_in[0];
    const int*   send  = (const int*)d_in[1];
    const int*   recv  = (const int*)d_in[2];
    const float* Wq0 = (const float*)d_in[3];
    const float* bq0 = (const float*)d_in[4];
    const float* Wl0 = (const float*)d_in[5];
    const float* bl0 = (const float*)d_in[6];
    const float* Wq1 = (const float*)d_in[7];
    const float* bq1 = (const float*)d_in[8];
    const float* Wl1 = (const float*)d_in[9];
    const float* bl1 = (const float*)d_in[10];
    const float* Wq2 = (const float*)d_in[11];
    const float* bq2 = (const float*)d_in[12];
    const float* Wl2 = (const float*)d_in[13];
    const float* bl2 = (const float*)d_in[14];
    float* out = (float*)d_out;

    float *h, *x;
    int *deg, *off, *cur, *csr;
    cudaGetSymbolAddress((void**)&h,   g_h);
    cudaGetSymbolAddress((void**)&x,   g_x);
    cudaGetSymbolAddress((void**)&deg, g_deg);
    cudaGetSymbolAddress((void**)&off, g_off);
    cudaGetSymbolAddress((void**)&cur, g_cur);
    cudaGetSymbolAddress((void**)&csr, g_csr);

    int gemm_blocks = (N_NODES + 63) / 64;
    int edge_blocks = (N_NODES * 32 + 255) / 256;

    // launch index 3 (k_gemm layer0) is the one ncu profiles — keep it there.
    k_count<<<(N_EDGES + 255) / 256, 256>>>(recv, deg, N_EDGES);          // 0
    k_scan<<<1, 1024>>>(deg, off, cur, N_NODES);                          // 1
    k_scatter<<<(N_EDGES + 255) / 256, 256>>>(recv, send, cur, csr, deg, N_EDGES); // 2
    k_gemm<<<gemm_blocks, 256>>>(nodes, Wq0, bq0, h, N_NODES, 128);       // 3 (profiled)
    k_edge<<<edge_blocks, 256>>>(h, off, csr, Wl0, bl0, x, N_NODES, 0);   // 4
    k_gemm<<<gemm_blocks, 256>>>(x, Wq1, bq1, h, N_NODES, D1);            // 5
    k_edge<<<edge_blocks, 256>>>(h, off, csr, Wl1, bl1, x, N_NODES, 0);   // 6
    k_gemm<<<gemm_blocks, 256>>>(x, Wq2, bq2, h, N_NODES, D1);            // 7
    k_edge<<<edge_blocks, 256>>>(h, off, csr, Wl2, bl2, out, N_NODES, 1); // 8
}